// round 3
// baseline (speedup 1.0000x reference)
#include <cuda_runtime.h>

#define N_ENTITY 100000
#define N_RELS   500
#define DIM      128
#define NTRIP    250000
#define NBATCH   500000
#define BNEPS    1e-5f
#define OUT_ENT  (N_ENTITY*DIM)

typedef unsigned long long ull;

// ---------------- scratch (static device globals; no allocation) ----------------
__device__ __align__(16) float g_PI[N_ENTITY*256];   // interleaved P0'(=P0+d) | P1 per entity
__device__ __align__(16) float g_Q [N_RELS*DIM];
__device__ __align__(16) float g_Gt [DIM*256];       // [k][jj] jj<128 -> G0, else G1
__device__ __align__(16) float g_Grt[DIM*DIM];       // [k][j]
__device__ int   g_icntE[N_ENTITY];
__device__ int   g_icntR[N_RELS];
__device__ __align__(16) float g_stats4[512];        // [0:128)=sumE [128:256)=sumE2 [256:384)=varR [384:512)=sumZ2
__device__ __align__(16) float g_d[DIM];
__device__ __align__(16) float g_ac[DIM], g_dc[DIM], g_wt[DIM];
__device__ __align__(16) float g_u0[DIM], g_u1[DIM];
__device__ float g_Sc;
__device__ float g_s0[N_ENTITY], g_s1[N_ENTITY], g_sq[N_RELS];
// CSR machinery
__device__ int g_offL[N_ENTITY];
__device__ int g_bsum[128], g_bbase[128];
__device__ int g_off[N_ENTITY], g_cur[N_ENTITY];
__device__ int g_offR[N_RELS], g_curR[N_RELS];
__device__ int g_inc [2*NTRIP];   // edge*2 + role
__device__ int g_incR[NTRIP];

// ---------------- helpers ----------------
__device__ __forceinline__ float4 f4add(float4 a, float4 b){ return make_float4(a.x+b.x,a.y+b.y,a.z+b.z,a.w+b.w); }
__device__ __forceinline__ float4 f4sub(float4 a, float4 b){ return make_float4(a.x-b.x,a.y-b.y,a.z-b.z,a.w-b.w); }
__device__ __forceinline__ float4 f4mul(float4 a, float4 b){ return make_float4(a.x*b.x,a.y*b.y,a.z*b.z,a.w*b.w); }
__device__ __forceinline__ float4 ldg4(const float4* p){ return __ldg(p); }
__device__ __forceinline__ float lrexp(float s){ return expf(s >= 0.f ? -s : -0.01f*s); }

// ---------------- kernels ----------------
__global__ void k_count(const int* __restrict__ trip){
    int i = blockIdx.x*blockDim.x + threadIdx.x;
    if (i < NTRIP){
        atomicAdd(&g_icntE[trip[3*i]], 1);
        atomicAdd(&g_icntE[trip[3*i+1]], 1);
        atomicAdd(&g_icntR[trip[3*i+2]], 1);
    }
}

// fused count-weighted BN0 stats: ent blocks [0,800), rel blocks [800,863)
__global__ void k_stats(const float* __restrict__ E, const float* __restrict__ R){
    int j = threadIdx.x;                 // 128
    if (blockIdx.x < 800){
        int e0 = blockIdx.x*125, e1 = min(e0+125, N_ENTITY);
        float a1 = 0.f, a2 = 0.f;
        for (int e = e0; e < e1; e++){
            float c = (float)g_icntE[e];
            if (c != 0.f){
                float v = E[e*DIM + j];
                a1 += c*v;
                a2 += c*v*v;
            }
        }
        atomicAdd(&g_stats4[j], a1);
        atomicAdd(&g_stats4[128 + j], a2);
    } else {
        int b = blockIdx.x - 800;
        int r0 = b*8, r1 = min(r0 + 8, N_RELS);
        float a = 0.f;
        for (int r = r0; r < r1; r++){
            float v = R[r*DIM + j];
            a += (float)g_icntR[r]*v*v;
        }
        atomicAdd(&g_stats4[256 + j], a);
    }
}

// fused bn0 finalize + G materialization. grid 129 x 256.
__global__ void k_bn0makeG(const float* __restrict__ a_w, const float* __restrict__ a_b,
                           const float* __restrict__ bn0_g, const float* __restrict__ bn0_b){
    const float inv = 1.f/(float)NBATCH;
    if (blockIdx.x < 128){
        int k = blockIdx.x, jj = threadIdx.x;
        float m  = g_stats4[k]*inv;
        float v  = g_stats4[128 + k]*inv - m*m;
        float rs = rsqrtf(v + BNEPS);
        float a0 = bn0_g[k]*rs;
        float a1 = bn0_g[128 + k]*rs;
        float vr = g_stats4[256 + k]*(1.f/(float)NTRIP);   // mean of r-cols is exactly 0
        float ar = bn0_g[256 + k]*rsqrtf(vr + BNEPS);
        int j = jj & 127;
        float al = (jj < 128) ? a0 : a1;
        int col  = (jj < 128) ? k : 128 + k;
        g_Gt[k*256 + jj] = a_w[j*384 + col]*al;
        if (jj < 128) g_Grt[k*128 + jj] = a_w[jj*384 + 256 + k]*ar;
    } else {
        __shared__ float dsh[384];
        int j = threadIdx.x;
        if (j < 128){
            float m  = g_stats4[j]*inv;
            float v  = g_stats4[128 + j]*inv - m*m;
            float rs = rsqrtf(v + BNEPS);
            float a0 = bn0_g[j]*rs;
            float a1 = bn0_g[128 + j]*rs;
            dsh[j]       = bn0_b[j]       - m*a0;
            dsh[128 + j] = bn0_b[128 + j] - m*a1;
            dsh[256 + j] = bn0_b[256 + j];
        }
        __syncthreads();
        if (j < 128){
            float acc = a_b[j];
            #pragma unroll 8
            for (int k = 0; k < 384; k++) acc += a_w[j*384 + k]*dsh[k];
            g_d[j] = acc;
        }
    }
}

// P = E * G^T into interleaved layout; d folded into P0 half. f32x2 packed FMA.
__global__ void __launch_bounds__(256) k_pgemm(const float* __restrict__ E){
    __shared__ float As[128*32];
    __shared__ float Bs[32*128];
    int tid = threadIdx.x;
    int tx = tid & 15, ty = tid >> 4;
    int e0 = blockIdx.x*128;
    int jh = blockIdx.y;

    ull acc2[8][4];
    #pragma unroll
    for (int i = 0; i < 8; i++)
        #pragma unroll
        for (int r = 0; r < 4; r++) acc2[i][r] = 0ull;

    for (int kt = 0; kt < 128; kt += 32){
        #pragma unroll
        for (int i = 0; i < 4; i++){
            int lin = tid + i*256;
            int m  = lin >> 3;
            int k4 = (lin & 7) << 2;
            float4 v = make_float4(0.f,0.f,0.f,0.f);
            if (e0 + m < N_ENTITY) v = *(const float4*)&E[(e0+m)*DIM + kt + k4];
            *(float4*)&As[m*32 + k4] = v;
        }
        #pragma unroll
        for (int i = 0; i < 4; i++){
            int lin = tid + i*256;
            int k  = lin >> 5;
            int j4 = (lin & 31) << 2;
            *(float4*)&Bs[k*128 + j4] = *(const float4*)&g_Gt[(kt+k)*256 + jh*128 + j4];
        }
        __syncthreads();
        #pragma unroll
        for (int k = 0; k < 32; k++){
            double2 bl0 = *(const double2*)&Bs[k*128 + tx*8];
            double2 bl1 = *(const double2*)&Bs[k*128 + tx*8 + 4];
            ull b2[4];
            b2[0] = __double_as_longlong(bl0.x);
            b2[1] = __double_as_longlong(bl0.y);
            b2[2] = __double_as_longlong(bl1.x);
            b2[3] = __double_as_longlong(bl1.y);
            #pragma unroll
            for (int i = 0; i < 8; i++){
                unsigned ab = __float_as_uint(As[(ty*8 + i)*32 + k]);
                ull a2;
                asm("mov.b64 %0, {%1, %1};" : "=l"(a2) : "r"(ab));
                #pragma unroll
                for (int r = 0; r < 4; r++)
                    asm("fma.rn.f32x2 %0, %1, %2, %0;" : "+l"(acc2[i][r]) : "l"(a2), "l"(b2[r]));
            }
        }
        __syncthreads();
    }
    float4 dA = make_float4(0,0,0,0), dB = make_float4(0,0,0,0);
    if (jh == 0){
        dA = *(const float4*)&g_d[tx*8];
        dB = *(const float4*)&g_d[tx*8 + 4];
    }
    #pragma unroll
    for (int i = 0; i < 8; i++){
        int e = e0 + ty*8 + i;
        if (e < N_ENTITY){
            float4 v0, v1;
            v0.x = __uint_as_float((unsigned)(acc2[i][0]))       + dA.x;
            v0.y = __uint_as_float((unsigned)(acc2[i][0] >> 32)) + dA.y;
            v0.z = __uint_as_float((unsigned)(acc2[i][1]))       + dA.z;
            v0.w = __uint_as_float((unsigned)(acc2[i][1] >> 32)) + dA.w;
            v1.x = __uint_as_float((unsigned)(acc2[i][2]))       + dB.x;
            v1.y = __uint_as_float((unsigned)(acc2[i][2] >> 32)) + dB.y;
            v1.z = __uint_as_float((unsigned)(acc2[i][3]))       + dB.z;
            v1.w = __uint_as_float((unsigned)(acc2[i][3] >> 32)) + dB.w;
            *(float4*)&g_PI[e*256 + jh*128 + tx*8]     = v0;
            *(float4*)&g_PI[e*256 + jh*128 + tx*8 + 4] = v1;
        }
    }
}

__global__ void k_qgemm(const float* __restrict__ R){
    __shared__ float Rs[128];
    int rho = blockIdx.x, j = threadIdx.x;
    Rs[j] = R[rho*DIM + j];
    __syncthreads();
    float acc = 0.f;
    #pragma unroll 8
    for (int k = 0; k < 128; k++) acc += Rs[k]*g_Grt[k*128 + j];
    g_Q[rho*DIM + j] = acc;
}

// ---- CSR build: scanA -> scanB -> scanC -> fill ----
__global__ void k_scanA(){                         // grid 98 x 1024
    __shared__ int sh[1024];
    int t = threadIdx.x;
    int g = blockIdx.x*1024 + t;
    int v = (g < N_ENTITY) ? g_icntE[g] : 0;
    sh[t] = v; __syncthreads();
    #pragma unroll
    for (int off = 1; off < 1024; off <<= 1){
        int add = (t >= off) ? sh[t - off] : 0;
        __syncthreads();
        sh[t] += add;
        __syncthreads();
    }
    if (g < N_ENTITY) g_offL[g] = sh[t] - v;       // exclusive
    if (t == 1023) g_bsum[blockIdx.x] = sh[1023];
}

__global__ void k_scanB(){                         // 1 x 1024
    __shared__ int sh[1024];
    int t = threadIdx.x;
    int v = (t < 98) ? g_bsum[t] : 0;
    sh[t] = v; __syncthreads();
    #pragma unroll
    for (int off = 1; off < 1024; off <<= 1){
        int add = (t >= off) ? sh[t - off] : 0;
        __syncthreads();
        sh[t] += add;
        __syncthreads();
    }
    if (t < 98) g_bbase[t] = sh[t] - v;
    __syncthreads();
    int v2 = (t < N_RELS) ? g_icntR[t] : 0;
    sh[t] = v2; __syncthreads();
    #pragma unroll
    for (int off = 1; off < 1024; off <<= 1){
        int add = (t >= off) ? sh[t - off] : 0;
        __syncthreads();
        sh[t] += add;
        __syncthreads();
    }
    if (t < N_RELS){ int o = sh[t] - v2; g_offR[t] = o; g_curR[t] = o; }
}

__global__ void k_scanC(){                         // grid 98 x 1024
    int g = blockIdx.x*1024 + threadIdx.x;
    if (g < N_ENTITY){
        int o = g_offL[g] + g_bbase[g >> 10];
        g_off[g] = o; g_cur[g] = o;
    }
}

__global__ void k_fill(const int* __restrict__ trip){
    int i = blockIdx.x*blockDim.x + threadIdx.x;
    if (i < NTRIP){
        int t0 = trip[3*i], t1 = trip[3*i+1], t2 = trip[3*i+2];
        int p0 = atomicAdd(&g_cur[t0], 1);
        g_inc[p0] = i*2;
        int p1 = atomicAdd(&g_cur[t1], 1);
        g_inc[p1] = i*2 + 1;
        int pr = atomicAdd(&g_curR[t2], 1);
        g_incR[pr] = i;
    }
}

// pass D1: accumulate Σz^2 over all 2*NTRIP rows (warp per triplet). Σz is analytic.
__global__ void k_bn1stats(const int* __restrict__ trip){
    int lane = threadIdx.x & 31;
    int warp = (blockIdx.x*blockDim.x + threadIdx.x) >> 5;
    int nw   = (gridDim.x*blockDim.x) >> 5;
    const float4* PI4 = (const float4*)g_PI;
    const float4* Q4  = (const float4*)g_Q;
    float4 s2v = make_float4(0.f,0.f,0.f,0.f);
    for (int i = warp; i < NTRIP; i += nw){
        int t0 = trip[3*i], t1 = trip[3*i+1], t2 = trip[3*i+2];
        float4 p00 = ldg4(&PI4[t0*64 + lane]);        // P0'[t0]
        float4 p10 = ldg4(&PI4[t0*64 + 32 + lane]);   // P1[t0]
        float4 p01 = ldg4(&PI4[t1*64 + lane]);        // P0'[t1]
        float4 p11 = ldg4(&PI4[t1*64 + 32 + lane]);   // P1[t1]
        float4 q   = ldg4(&Q4 [t2*32 + lane]);
        float4 zf = f4add(f4add(p00, p11), q);
        float4 zb = f4sub(f4add(p01, p10), q);
        s2v = f4add(s2v, f4add(f4mul(zf,zf), f4mul(zb,zb)));
    }
    int j4 = lane*4;
    atomicAdd(&g_stats4[384 + j4 + 0], s2v.x);
    atomicAdd(&g_stats4[384 + j4 + 1], s2v.y);
    atomicAdd(&g_stats4[384 + j4 + 2], s2v.z);
    atomicAdd(&g_stats4[384 + j4 + 3], s2v.w);
}

__global__ void k_bn1fin(const float* __restrict__ a2_w, const float* __restrict__ a2_b,
                         const float* __restrict__ bn1_g, const float* __restrict__ bn1_b){
    __shared__ float wts[128];
    __shared__ float red[128];
    int j = threadIdx.x;
    // analytic Σz: Q terms cancel between fwd/bwd rows
    float sz = 0.f;
    #pragma unroll 4
    for (int k = 0; k < 128; k++){
        float se = g_stats4[k];
        sz += se*(g_Gt[k*256 + j] + g_Gt[k*256 + 128 + j]);
    }
    float dj = g_d[j];
    sz += 2.f*(float)NTRIP*dj;
    const float inv = 1.f/(float)NBATCH;
    float mz = sz*inv;
    float vz = g_stats4[384 + j]*inv - mz*mz;
    float ac = bn1_g[j]*rsqrtf(vz + BNEPS);
    float dc = bn1_b[j] - mz*ac;
    g_ac[j] = ac; g_dc[j] = dc;
    float w = a2_w[j]*ac;
    g_wt[j] = w;
    wts[j] = w;
    red[j] = w*dj + a2_w[j]*dc;
    __syncthreads();
    float u0 = 0.f, u1 = 0.f;
    #pragma unroll 4
    for (int jj = 0; jj < 128; jj++){
        float wv = wts[jj];
        u0 += wv*g_Gt[j*256 + jj];
        u1 += wv*g_Gt[j*256 + 128 + jj];
    }
    g_u0[j] = u0; g_u1[j] = u1;
    for (int s = 64; s > 0; s >>= 1){
        if (j < s) red[j] += red[j+s];
        __syncthreads();
    }
    if (j == 0) g_Sc = red[0] + a2_b[0];
}

// s0[e]=E[e]·u0, s1[e]=E[e]·u1 (ent jobs), sq[r]=wt·Q[r] (rel jobs)
__global__ void k_sentsq(const float* __restrict__ E){
    int lane = threadIdx.x & 31;
    int warp = (blockIdx.x*blockDim.x + threadIdx.x) >> 5;
    int nw   = (gridDim.x*blockDim.x) >> 5;
    float4 u04 = ((const float4*)g_u0)[lane];
    float4 u14 = ((const float4*)g_u1)[lane];
    const float4* E4 = (const float4*)E;
    const float4* Q4 = (const float4*)g_Q;
    for (int job = warp; job < N_ENTITY + N_RELS; job += nw){
        if (job < N_ENTITY){
            float4 v = ldg4(&E4[job*32 + lane]);
            float d0 = v.x*u04.x + v.y*u04.y + v.z*u04.z + v.w*u04.w;
            float d1 = v.x*u14.x + v.y*u14.y + v.z*u14.z + v.w*u14.w;
            #pragma unroll
            for (int off = 16; off > 0; off >>= 1){
                d0 += __shfl_down_sync(0xffffffffu, d0, off);
                d1 += __shfl_down_sync(0xffffffffu, d1, off);
            }
            if (lane == 0){ g_s0[job] = d0; g_s1[job] = d1; }
        } else {
            int r = job - N_ENTITY;
            float4 w4 = ((const float4*)g_wt)[lane];
            float4 p  = Q4[r*32 + lane];
            float d0 = p.x*w4.x + p.y*w4.y + p.z*w4.z + p.w*w4.w;
            #pragma unroll
            for (int off = 16; off > 0; off >>= 1)
                d0 += __shfl_down_sync(0xffffffffu, d0, off);
            if (lane == 0) g_sq[r] = d0;
        }
    }
}

// atomic-free entity aggregation: warp per entity, CSR incidences
__global__ void __launch_bounds__(256) k_ent(const int* __restrict__ trip, float* __restrict__ out){
    int lane = threadIdx.x & 31;
    int e = (blockIdx.x*blockDim.x + threadIdx.x) >> 5;
    if (e >= N_ENTITY) return;
    const float4* PI4 = (const float4*)g_PI;
    const float4* Q4  = (const float4*)g_Q;
    float4 own = PI4[e*64 + lane];        // P0'[e] (includes d)
    float  s0e = g_s0[e];
    float  Sc  = g_Sc;
    int base = g_off[e], cnt = g_icntE[e];
    float4 acc = make_float4(0.f,0.f,0.f,0.f);
    float wsum = 0.f;
    for (int k = 0; k < cnt; k++){
        int ent = g_inc[base + k];
        int i = ent >> 1, role = ent & 1;
        int t0 = trip[3*i], t1 = trip[3*i+1], t2 = trip[3*i+2];
        int other = role ? t0 : t1;
        float sgn = role ? -1.f : 1.f;
        float s = s0e + g_s1[other] + sgn*g_sq[t2] + Sc;
        float w = lrexp(s);
        float4 p = ldg4(&PI4[other*64 + 32 + lane]);   // P1[other]
        float4 q = ldg4(&Q4[t2*32 + lane]);
        acc.x += w*(p.x + sgn*q.x);
        acc.y += w*(p.y + sgn*q.y);
        acc.z += w*(p.z + sgn*q.z);
        acc.w += w*(p.w + sgn*q.w);
        wsum += w;
    }
    float4 a = ((const float4*)g_ac)[lane];
    float4 d = ((const float4*)g_dc)[lane];
    float den = (wsum == 0.f) ? 1e-12f : wsum;
    float inv = 1.f/den;
    float4 o;
    o.x = (a.x*(wsum*own.x + acc.x) + d.x*wsum)*inv;
    o.y = (a.y*(wsum*own.y + acc.y) + d.y*wsum)*inv;
    o.z = (a.z*(wsum*own.z + acc.z) + d.z*wsum)*inv;
    o.w = (a.w*(wsum*own.w + acc.w) + d.w*wsum)*inv;
    *(float4*)&out[(size_t)e*DIM + lane*4] = o;
}

// atomic-free relation aggregation: block per relation (8 warps)
__global__ void __launch_bounds__(256) k_rel(const int* __restrict__ trip, float* __restrict__ out){
    __shared__ float sm[8][128];
    __shared__ float sw[8];
    int r = blockIdx.x;
    int lane = threadIdx.x & 31;
    int wrp  = threadIdx.x >> 5;
    const float4* PI4 = (const float4*)g_PI;
    float4 q = ((const float4*)g_Q)[r*32 + lane];
    float sqv = g_sq[r];
    float Sc  = g_Sc;
    int base = g_offR[r], cnt = g_icntR[r];
    float4 acc = make_float4(0.f,0.f,0.f,0.f);
    float wsum = 0.f;
    for (int k = wrp; k < cnt; k += 8){
        int i = g_incR[base + k];
        int t0 = trip[3*i], t1 = trip[3*i+1];
        float s = g_s0[t0] + g_s1[t1] + sqv + Sc;
        float w = lrexp(s);
        float4 pa = ldg4(&PI4[t0*64 + lane]);        // P0'[t0]
        float4 pb = ldg4(&PI4[t1*64 + 32 + lane]);   // P1[t1]
        acc.x += w*(pa.x + pb.x + q.x);
        acc.y += w*(pa.y + pb.y + q.y);
        acc.z += w*(pa.z + pb.z + q.z);
        acc.w += w*(pa.w + pb.w + q.w);
        wsum += w;
    }
    *(float4*)&sm[wrp][lane*4] = acc;
    #pragma unroll
    for (int off = 16; off > 0; off >>= 1) wsum += __shfl_down_sync(0xffffffffu, wsum, off);
    if (lane == 0) sw[wrp] = wsum;
    __syncthreads();
    int t = threadIdx.x;
    if (t < 128){
        float tot = 0.f;
        #pragma unroll
        for (int w = 0; w < 8; w++) tot += sm[w][t];
        float W = 0.f;
        #pragma unroll
        for (int w = 0; w < 8; w++) W += sw[w];
        float invc = 1.f/fmaxf((float)cnt, 1.f);
        out[OUT_ENT + (size_t)r*DIM + t] = (g_ac[t]*tot + g_dc[t]*W)*invc;
    }
}

// ---------------- launcher ----------------
extern "C" void kernel_launch(void* const* d_in, const int* in_sizes, int n_in,
                              void* d_out, int out_size){
    const int*   trip  = (const int*)  d_in[0];
    const float* E     = (const float*)d_in[1];
    const float* R     = (const float*)d_in[2];
    const float* a_w   = (const float*)d_in[3];
    const float* a_b   = (const float*)d_in[4];
    const float* a2_w  = (const float*)d_in[5];
    const float* a2_b  = (const float*)d_in[6];
    const float* bn0_g = (const float*)d_in[7];
    const float* bn0_b = (const float*)d_in[8];
    const float* bn1_g = (const float*)d_in[9];
    const float* bn1_b = (const float*)d_in[10];
    float* out = (float*)d_out;

    void *pIcE, *pIcR, *pSt;
    cudaGetSymbolAddress(&pIcE, g_icntE);
    cudaGetSymbolAddress(&pIcR, g_icntR);
    cudaGetSymbolAddress(&pSt,  g_stats4);
    cudaMemsetAsync(pIcE, 0, N_ENTITY*sizeof(int));
    cudaMemsetAsync(pIcR, 0, N_RELS*sizeof(int));
    cudaMemsetAsync(pSt,  0, 512*sizeof(float));

    k_count<<<(NTRIP + 255)/256, 256>>>(trip);
    k_stats<<<863, 128>>>(E, R);
    k_bn0makeG<<<129, 256>>>(a_w, a_b, bn0_g, bn0_b);
    k_pgemm<<<dim3(782, 2), 256>>>(E);
    k_qgemm<<<N_RELS, 128>>>(R);
    k_scanA<<<98, 1024>>>();
    k_scanB<<<1, 1024>>>();
    k_scanC<<<98, 1024>>>();
    k_fill<<<(NTRIP + 255)/256, 256>>>(trip);
    k_bn1stats<<<2048, 256>>>(trip);
    k_bn1fin<<<1, 128>>>(a2_w, a2_b, bn1_g, bn1_b);
    k_sentsq<<<800, 256>>>(E);
    k_ent<<<(N_ENTITY*32 + 255)/256, 256>>>(trip, out);
    k_rel<<<N_RELS, 256>>>(trip, out);
}